// round 6
// baseline (speedup 1.0000x reference)
#include <cuda_runtime.h>

// Problem shape
#define NB   32      // batch
#define NT   1000    // time steps
#define NO   1024    // n_out
#define NI   1024    // n_in (K)

// currents scratch: [b][t][o]  (32 * 1000 * 1024 floats = 131 MB)
__device__ float g_cur[(size_t)NB * NT * NO];

// ---------------------------------------------------------------------------
// GEMM: cur[b][t][o] = sum_i x[b][i][t] * w[i][o]
// TWO-LEVEL ACCUMULATION for low rounding error (~3x lower than a single
// sequential FMA chain): each BK=16 k-chunk accumulates into a fresh chunk
// register, which is then folded into the master accumulator (64 folds total).
// Tile: BM=128 (t), BN=128 (o), BK=16; 256 threads; 8x8 per-thread microtile.
// ---------------------------------------------------------------------------
__global__ __launch_bounds__(256, 1)
void snn_gemm_kernel(const float* __restrict__ x, const float* __restrict__ w)
{
    const int BM = 128, BN = 128, BK = 16;
    __shared__ float As[BK][BM];
    __shared__ float Bs[BK][BN];

    const int b  = blockIdx.z;
    const int t0 = blockIdx.y * BM;
    const int n0 = blockIdx.x * BN;

    const float* __restrict__ xb = x + (size_t)b * NI * NT;

    const int tid = threadIdx.x;
    const int tx  = tid & 15;   // 0..15 -> n microtile
    const int ty  = tid >> 4;   // 0..15 -> m microtile

    float acc[8][8];   // master accumulator
#pragma unroll
    for (int i = 0; i < 8; i++)
#pragma unroll
        for (int j = 0; j < 8; j++) acc[i][j] = 0.0f;

    for (int k0 = 0; k0 < NI; k0 += BK) {
        // Load A tile: 16 k-rows x 128 t-cols = 512 float4 total, 2 per thread.
#pragma unroll
        for (int l = 0; l < 2; l++) {
            int idx = tid + l * 256;        // 0..511
            int kk  = idx >> 5;             // 0..15
            int m4  = (idx & 31) << 2;      // 0..124
            int t   = t0 + m4;
            float4 v = make_float4(0.f, 0.f, 0.f, 0.f);
            if (t < NT) {
                // (k*1000 + t) is a multiple of 4 -> 16B aligned
                v = *reinterpret_cast<const float4*>(xb + (size_t)(k0 + kk) * NT + t);
            }
            *reinterpret_cast<float4*>(&As[kk][m4]) = v;
        }
        // Load B tile: 16 k-rows x 128 o-cols.
#pragma unroll
        for (int l = 0; l < 2; l++) {
            int idx = tid + l * 256;
            int kk  = idx >> 5;
            int n4  = (idx & 31) << 2;
            *reinterpret_cast<float4*>(&Bs[kk][n4]) =
                *reinterpret_cast<const float4*>(w + (size_t)(k0 + kk) * NO + n0 + n4);
        }
        __syncthreads();

        // Chunk accumulator for this BK slice (starts at 0 -> small magnitudes,
        // small rounding; folded once into master below).
        float cacc[8][8];
#pragma unroll
        for (int i = 0; i < 8; i++)
#pragma unroll
            for (int j = 0; j < 8; j++) cacc[i][j] = 0.0f;

#pragma unroll
        for (int kk = 0; kk < BK; kk++) {
            float a[8], bb[8];
            float4 a0 = *reinterpret_cast<const float4*>(&As[kk][ty * 8]);
            float4 a1 = *reinterpret_cast<const float4*>(&As[kk][ty * 8 + 4]);
            float4 b0 = *reinterpret_cast<const float4*>(&Bs[kk][tx * 8]);
            float4 b1 = *reinterpret_cast<const float4*>(&Bs[kk][tx * 8 + 4]);
            a[0]=a0.x; a[1]=a0.y; a[2]=a0.z; a[3]=a0.w;
            a[4]=a1.x; a[5]=a1.y; a[6]=a1.z; a[7]=a1.w;
            bb[0]=b0.x; bb[1]=b0.y; bb[2]=b0.z; bb[3]=b0.w;
            bb[4]=b1.x; bb[5]=b1.y; bb[6]=b1.z; bb[7]=b1.w;
#pragma unroll
            for (int i = 0; i < 8; i++)
#pragma unroll
                for (int j = 0; j < 8; j++)
                    cacc[i][j] = __fmaf_rn(a[i], bb[j], cacc[i][j]);
        }

        // Fold chunk into master (one rounding at full magnitude per 16 k's).
#pragma unroll
        for (int i = 0; i < 8; i++)
#pragma unroll
            for (int j = 0; j < 8; j++)
                acc[i][j] = __fadd_rn(acc[i][j], cacc[i][j]);

        __syncthreads();
    }

    // Store C tile into g_cur[b][t][o]
    float* __restrict__ cb = g_cur + (size_t)b * NT * NO;
#pragma unroll
    for (int i = 0; i < 8; i++) {
        int t = t0 + ty * 8 + i;
        if (t < NT) {
            float* row = cb + (size_t)t * NO + n0 + tx * 8;
            float4 v0 = make_float4(acc[i][0], acc[i][1], acc[i][2], acc[i][3]);
            float4 v1 = make_float4(acc[i][4], acc[i][5], acc[i][6], acc[i][7]);
            *reinterpret_cast<float4*>(row)     = v0;
            *reinterpret_cast<float4*>(row + 4) = v1;
        }
    }
}

// ---------------------------------------------------------------------------
// Scan: per (b,o) neuron, serial over t (exact reference rounding order,
// verified: fma-vs-separate made zero output difference, scan is exact).
// ---------------------------------------------------------------------------
#define TT 40   // 1000 % 40 == 0

__global__ __launch_bounds__(128)
void snn_scan_kernel(float* __restrict__ out)
{
    __shared__ float s[128][TT + 1];

    const int b  = blockIdx.y;
    const int o0 = blockIdx.x * 128;
    const int o  = o0 + threadIdx.x;

    const float* __restrict__ cb = g_cur + (size_t)b * NT * NO;
    const float DT = (float)(0.001 / 50.0);   // f32(MS/TAU)

    float v = 0.0f;

    for (int tc = 0; tc < NT; tc += TT) {
#pragma unroll
        for (int tt = 0; tt < TT; tt++) {
            float cur = cb[(size_t)(tc + tt) * NO + o];
            float d  = __fsub_rn(cur, v);
            float dv = __fmul_rn(d, DT);
            v = __fadd_rn(v, dv);
            bool sp = (v >= 1.0f);
            s[threadIdx.x][tt] = sp ? 1.0f : 0.0f;
            v = sp ? 0.0f : v;
        }
        __syncthreads();

        // Transposed, coalesced-along-t store
        for (int idx = threadIdx.x; idx < 128 * TT; idx += 128) {
            int oo = idx / TT;
            int tt = idx - oo * TT;
            out[((size_t)b * NO + (o0 + oo)) * NT + tc + tt] = s[oo][tt];
        }
        __syncthreads();
    }
}

// ---------------------------------------------------------------------------
extern "C" void kernel_launch(void* const* d_in, const int* in_sizes, int n_in,
                              void* d_out, int out_size)
{
    const float* x = (const float*)d_in[0];   // [32, 1024, 1000]
    const float* w = (const float*)d_in[1];   // [1024, 1024]
    float* out = (float*)d_out;               // [32, 1024, 1000]

    (void)in_sizes; (void)n_in; (void)out_size;

    dim3 ggrid(NO / 128, (NT + 127) / 128, NB);   // 8 x 8 x 32
    snn_gemm_kernel<<<ggrid, 256>>>(x, w);

    dim3 sgrid(NO / 128, NB);                     // 8 x 32
    snn_scan_kernel<<<sgrid, 128>>>(out);
}

// round 7
// speedup vs baseline: 1.0349x; 1.0349x over previous
#include <cuda_runtime.h>

typedef unsigned long long ull;

// Problem shape
#define NB   32      // batch
#define NT   1000    // time steps
#define NO   1024    // n_out
#define NI   1024    // n_in (K)

// currents scratch: [b][t][o]  (32 * 1000 * 1024 floats = 131 MB)
__device__ float g_cur[(size_t)NB * NT * NO];

// ---------------------------------------------------------------------------
// GEMM: cur[b][t][o] = sum_i x[b][i][t] * w[i][o]
// BIT-EXACT accumulation (verified rel_err==0.0): per output element, a
// fresh BK=16 chunk FMA chain (k ascending) folded into a master accumulator
// with a plain rn add, chunks ascending. This structure is FROZEN.
// Speed: packed fma.rn.f32x2 (FFMA2) — each lane is an independent IEEE-rn
// fp32 FMA, so packing two adjacent o-columns per 64-bit register preserves
// every element's rounding order exactly while doubling flops/issue.
// Tile: BM=128 (t), BN=128 (o), BK=16; 256 threads; 8x8 per-thread microtile.
// ---------------------------------------------------------------------------
__global__ __launch_bounds__(256, 1)
void snn_gemm_kernel(const float* __restrict__ x, const float* __restrict__ w)
{
    const int BM = 128, BN = 128, BK = 16;
    __shared__ float As[BK][BM];
    __shared__ float Bs[BK][BN];

    const int b  = blockIdx.z;
    const int t0 = blockIdx.y * BM;
    const int n0 = blockIdx.x * BN;

    const float* __restrict__ xb = x + (size_t)b * NI * NT;

    const int tid = threadIdx.x;
    const int tx  = tid & 15;   // 0..15 -> n microtile (8 floats = 4 f32x2)
    const int ty  = tid >> 4;   // 0..15 -> m microtile

    // Per-thread global-load coordinates (2 float4 for A, 2 for B)
    const int akk0 = tid >> 5;             // 0..7
    const int akk1 = akk0 + 8;             // 8..15
    const int am4  = (tid & 31) << 2;      // 0..124
    const int at   = t0 + am4;

    ull acc2[8][4];    // master accumulator, packed pairs of o
#pragma unroll
    for (int i = 0; i < 8; i++)
#pragma unroll
        for (int jp = 0; jp < 4; jp++) acc2[i][jp] = 0ull;

    // ---- prefetch tile 0 into registers ----
    float4 pa0, pa1, pb0, pb1;
    {
        const int k0 = 0;
        pa0 = make_float4(0.f, 0.f, 0.f, 0.f);
        pa1 = pa0;
        if (at < NT) {
            pa0 = *reinterpret_cast<const float4*>(xb + (size_t)(k0 + akk0) * NT + at);
            pa1 = *reinterpret_cast<const float4*>(xb + (size_t)(k0 + akk1) * NT + at);
        }
        pb0 = *reinterpret_cast<const float4*>(w + (size_t)(k0 + akk0) * NO + n0 + am4);
        pb1 = *reinterpret_cast<const float4*>(w + (size_t)(k0 + akk1) * NO + n0 + am4);
    }

    for (int k0 = 0; k0 < NI; k0 += BK) {
        // store prefetched tile to smem
        *reinterpret_cast<float4*>(&As[akk0][am4]) = pa0;
        *reinterpret_cast<float4*>(&As[akk1][am4]) = pa1;
        *reinterpret_cast<float4*>(&Bs[akk0][am4]) = pb0;
        *reinterpret_cast<float4*>(&Bs[akk1][am4]) = pb1;
        __syncthreads();

        // prefetch next tile (latency overlapped with compute below)
        const int kn = k0 + BK;
        if (kn < NI) {
            pa0 = make_float4(0.f, 0.f, 0.f, 0.f);
            pa1 = pa0;
            if (at < NT) {
                pa0 = *reinterpret_cast<const float4*>(xb + (size_t)(kn + akk0) * NT + at);
                pa1 = *reinterpret_cast<const float4*>(xb + (size_t)(kn + akk1) * NT + at);
            }
            pb0 = *reinterpret_cast<const float4*>(w + (size_t)(kn + akk0) * NO + n0 + am4);
            pb1 = *reinterpret_cast<const float4*>(w + (size_t)(kn + akk1) * NO + n0 + am4);
        }

        // Chunk accumulator (fresh per BK slice) — packed
        ull cacc2[8][4];
#pragma unroll
        for (int i = 0; i < 8; i++)
#pragma unroll
            for (int jp = 0; jp < 4; jp++) cacc2[i][jp] = 0ull;

#pragma unroll
        for (int kk = 0; kk < BK; kk++) {
            float4 a0 = *reinterpret_cast<const float4*>(&As[kk][ty * 8]);
            float4 a1 = *reinterpret_cast<const float4*>(&As[kk][ty * 8 + 4]);
            ulonglong2 q0 = *reinterpret_cast<const ulonglong2*>(&Bs[kk][tx * 8]);
            ulonglong2 q1 = *reinterpret_cast<const ulonglong2*>(&Bs[kk][tx * 8 + 4]);
            ull bp[4];
            bp[0] = q0.x; bp[1] = q0.y; bp[2] = q1.x; bp[3] = q1.y;
            float av[8];
            av[0]=a0.x; av[1]=a0.y; av[2]=a0.z; av[3]=a0.w;
            av[4]=a1.x; av[5]=a1.y; av[6]=a1.z; av[7]=a1.w;
#pragma unroll
            for (int i = 0; i < 8; i++) {
                ull a2;
                asm("mov.b64 %0, {%1, %1};" : "=l"(a2) : "f"(av[i]));
#pragma unroll
                for (int jp = 0; jp < 4; jp++) {
                    asm("fma.rn.f32x2 %0, %1, %2, %0;"
                        : "+l"(cacc2[i][jp])
                        : "l"(a2), "l"(bp[jp]));
                }
            }
        }

        // Fold chunk into master (rn add, lane-wise — identical to scalar)
#pragma unroll
        for (int i = 0; i < 8; i++)
#pragma unroll
            for (int jp = 0; jp < 4; jp++) {
                asm("add.rn.f32x2 %0, %0, %1;"
                    : "+l"(acc2[i][jp]) : "l"(cacc2[i][jp]));
            }

        __syncthreads();
    }

    // Store C tile into g_cur[b][t][o] (packed pairs are adjacent o's)
    float* __restrict__ cb = g_cur + (size_t)b * NT * NO;
#pragma unroll
    for (int i = 0; i < 8; i++) {
        int t = t0 + ty * 8 + i;
        if (t < NT) {
            float* row = cb + (size_t)t * NO + n0 + tx * 8;
            ulonglong2 v0, v1;
            v0.x = acc2[i][0]; v0.y = acc2[i][1];
            v1.x = acc2[i][2]; v1.y = acc2[i][3];
            *reinterpret_cast<ulonglong2*>(row)     = v0;
            *reinterpret_cast<ulonglong2*>(row + 4) = v1;
        }
    }
}

// ---------------------------------------------------------------------------
// Scan: per (b,o) neuron, serial over t (bit-exact reference rounding order).
// ---------------------------------------------------------------------------
#define TT 40   // 1000 % 40 == 0

__global__ __launch_bounds__(128)
void snn_scan_kernel(float* __restrict__ out)
{
    __shared__ float s[128][TT + 1];

    const int b  = blockIdx.y;
    const int o0 = blockIdx.x * 128;
    const int o  = o0 + threadIdx.x;

    const float* __restrict__ cb = g_cur + (size_t)b * NT * NO;
    const float DT = (float)(0.001 / 50.0);   // f32(MS/TAU)

    float v = 0.0f;

    for (int tc = 0; tc < NT; tc += TT) {
#pragma unroll
        for (int tt = 0; tt < TT; tt++) {
            float cur = cb[(size_t)(tc + tt) * NO + o];
            float d  = __fsub_rn(cur, v);
            float dv = __fmul_rn(d, DT);
            v = __fadd_rn(v, dv);
            bool sp = (v >= 1.0f);
            s[threadIdx.x][tt] = sp ? 1.0f : 0.0f;
            v = sp ? 0.0f : v;
        }
        __syncthreads();

        // Transposed, coalesced-along-t store
        for (int idx = threadIdx.x; idx < 128 * TT; idx += 128) {
            int oo = idx / TT;
            int tt = idx - oo * TT;
            out[((size_t)b * NO + (o0 + oo)) * NT + tc + tt] = s[oo][tt];
        }
        __syncthreads();
    }
}

// ---------------------------------------------------------------------------
extern "C" void kernel_launch(void* const* d_in, const int* in_sizes, int n_in,
                              void* d_out, int out_size)
{
    const float* x = (const float*)d_in[0];   // [32, 1024, 1000]
    const float* w = (const float*)d_in[1];   // [1024, 1024]
    float* out = (float*)d_out;               // [32, 1024, 1000]

    (void)in_sizes; (void)n_in; (void)out_size;

    dim3 ggrid(NO / 128, (NT + 127) / 128, NB);   // 8 x 8 x 32
    snn_gemm_kernel<<<ggrid, 256>>>(x, w);

    dim3 sgrid(NO / 128, NB);                     // 8 x 32
    snn_scan_kernel<<<sgrid, 128>>>(out);
}

// round 10
// speedup vs baseline: 1.0688x; 1.0328x over previous
#include <cuda_runtime.h>
#include <cuda_bf16.h>
#include <cstdint>

// ---------------------------------------------------------------------------
// Problem shape
#define NB   32      // batch
#define NT   1000    // time steps
#define NO   1024    // n_out
#define NI   1024    // n_in (K)
#define NTP  1024    // padded T

// Scratch (__device__ globals zero-initialized; pad rows stay zero)
__device__ float g_cur[(size_t)NB * NT * NO];            // currents [b][t][o]
__device__ float g_xt[(size_t)2 * NB * NTP * NI];        // x tf32 planes [p][b][t][k]
__device__ float g_wt[(size_t)2 * NO * NI];              // w tf32 planes [p][n][k]

__device__ __forceinline__ uint32_t smem_u32(const void* p) {
    uint32_t a;
    asm("{ .reg .u64 t; cvta.to.shared.u64 t, %1; cvt.u32.u64 %0, t; }" : "=r"(a) : "l"(p));
    return a;
}

// fp32 -> 2x tf32 split (residual ~ 2^-23 relative: near-exact)
__device__ __forceinline__ void split2_tf32(float v, float& t0, float& t1) {
    uint32_t u0, u1;
    asm("cvt.rna.tf32.f32 %0, %1;" : "=r"(u0) : "f"(v));
    float f0 = __uint_as_float(u0);
    float r = __fsub_rn(v, f0);
    asm("cvt.rna.tf32.f32 %0, %1;" : "=r"(u1) : "f"(r));
    t0 = f0; t1 = __uint_as_float(u1);
}

// ---------------------------------------------------------------------------
// wconv: w[k][n] (f32) -> g_wt[p][n][k] (tf32 planes, transposed)
// ---------------------------------------------------------------------------
__global__ __launch_bounds__(256)
void wconv_kernel(const float* __restrict__ w)
{
    __shared__ float tile[32][33];
    const int k0 = blockIdx.x * 32;
    const int n0 = blockIdx.y * 32;
    const int tx = threadIdx.x, ty = threadIdx.y;   // (32, 8)
#pragma unroll
    for (int j = 0; j < 4; j++) {
        int k = k0 + ty + 8 * j;
        tile[ty + 8 * j][tx] = w[(size_t)k * NO + n0 + tx];
    }
    __syncthreads();
#pragma unroll
    for (int j = 0; j < 4; j++) {
        int r = ty + 8 * j;
        int n = n0 + r;
        float t0, t1;
        split2_tf32(tile[tx][r], t0, t1);
        size_t base = (size_t)n * NI + k0 + tx;
        g_wt[base]                   = t0;
        g_wt[(size_t)NO * NI + base] = t1;
    }
}

// ---------------------------------------------------------------------------
// xconv: x[b][k][t] (f32) -> g_xt[p][b][t][k] (tf32 planes, transposed per b)
// ---------------------------------------------------------------------------
__global__ __launch_bounds__(256)
void xconv_kernel(const float* __restrict__ x)
{
    __shared__ float tile[32][33];
    const int b  = blockIdx.z;
    const int k0 = blockIdx.y * 32;
    const int t0 = blockIdx.x * 32;
    const int tx = threadIdx.x, ty = threadIdx.y;   // (32, 8)
    const float* xb = x + (size_t)b * NI * NT;
#pragma unroll
    for (int j = 0; j < 4; j++) {
        int k = k0 + ty + 8 * j;
        int t = t0 + tx;
        tile[ty + 8 * j][tx] = (t < NT) ? xb[(size_t)k * NT + t] : 0.0f;
    }
    __syncthreads();
    const size_t plane = (size_t)NB * NTP * NI;
#pragma unroll
    for (int j = 0; j < 4; j++) {
        int r = ty + 8 * j;
        int t = t0 + r;
        if (t < NT) {
            float t0f, t1f;
            split2_tf32(tile[tx][r], t0f, t1f);
            size_t base = ((size_t)b * NTP + t) * NI + k0 + tx;
            g_xt[base]         = t0f;
            g_xt[plane + base] = t1f;
        }
    }
}

// ---------------------------------------------------------------------------
// GEMM via mma.sync.m16n8k8.tf32 (sm_80 path, valid on compute_103).
// cur = sum_k x*w, fp32-emulated tf32x3: main = t0*t0' (two-level: zero-start
// chunk acc per BK=32, folded to master with rn add, chunks ascending —
// mirrors the verified-bit-exact R6 structure); corr = t0*t1' + t1*t0'.
// Block 256 thr (8 warps, 2m x 4n), CTA tile 128(t) x 128(o), BK=32
// double-buffered cp.async. Warp tile 64x32 (4 m16 x 4 n8).
// ---------------------------------------------------------------------------
#define PBY    16384             // one operand plane: 128 rows x 32 tf32 (128B rows)
#define BUFB   (4 * PBY)         // [A0][A1][B0][B1] = 64 KB
#define SMEMSZ (2 * BUFB)        // 128 KB
#define NC     32                // 1024 / 32 chunks

__device__ __forceinline__ void ldsm4(uint32_t* r, uint32_t addr) {
    asm volatile("ldmatrix.sync.aligned.m8n8.x4.shared.b16 {%0,%1,%2,%3}, [%4];"
        : "=r"(r[0]), "=r"(r[1]), "=r"(r[2]), "=r"(r[3]) : "r"(addr));
}
__device__ __forceinline__ void mma_tf32(float* d, const uint32_t* a, uint32_t b0, uint32_t b1) {
    asm volatile("mma.sync.aligned.m16n8k8.row.col.f32.tf32.tf32.f32 "
        "{%0,%1,%2,%3}, {%4,%5,%6,%7}, {%8,%9}, {%0,%1,%2,%3};"
        : "+f"(d[0]), "+f"(d[1]), "+f"(d[2]), "+f"(d[3])
        : "r"(a[0]), "r"(a[1]), "r"(a[2]), "r"(a[3]), "r"(b0), "r"(b1));
}

__device__ __forceinline__ void load_chunk(uint32_t sbuf,
                                           const float* xb, const float* wb,
                                           int k0, int tid,
                                           size_t xplane, size_t wplane)
{
    // 4096 16B chunks: [A0][A1][B0][B1], each 128 rows x 8 chunks
#pragma unroll
    for (int i = 0; i < 16; i++) {
        int v   = tid + i * 256;          // 0..4095
        int sec = v >> 10;                // 0..3
        int row = (v >> 3) & 127;
        int ch  = v & 7;
        const float* g;
        if (sec < 2) g = xb + (size_t)(sec)     * xplane + (size_t)row * NI + k0 + ch * 4;
        else         g = wb + (size_t)(sec - 2) * wplane + (size_t)row * NI + k0 + ch * 4;
        uint32_t d = sbuf + sec * PBY + row * 128 + ((ch ^ (row & 7)) * 16);
        asm volatile("cp.async.cg.shared.global [%0], [%1], 16;" :: "r"(d), "l"((const void*)g));
    }
}

__global__ __launch_bounds__(256, 1)
void snn_gemm_tf32()
{
    extern __shared__ char smem[];
    const int tid  = threadIdx.x;
    const int lane = tid & 31;
    const int wid  = tid >> 5;

    const int b  = blockIdx.z;
    const int t0 = blockIdx.y * 128;
    const int n0 = blockIdx.x * 128;

    const size_t xplane = (size_t)NB * NTP * NI;
    const size_t wplane = (size_t)NO * NI;
    const float* xb = g_xt + ((size_t)b * NTP + t0) * NI;
    const float* wb = g_wt + (size_t)n0 * NI;

    const uint32_t sb = smem_u32(smem);

    const int warp_m = (wid >> 2) * 64;    // 0 / 64
    const int warp_n = (wid & 3) * 32;     // 0..96

    // ldmatrix lane -> address components (b32-viewed 8x4 matrices)
    const int rA = lane & 15;              // A row (m-local within tile pair)
    const int hA = (lane >> 4) & 1;        // A k-half (0..1) -> 16B
    const int rB = (lane & 7) + ((lane >> 4) & 1) * 8;   // B row (n-local)
    const int hB = (lane >> 3) & 1;        // B k-half

    float accM[4][4][4], accC[4][4][4], accH[4][4][4];
#pragma unroll
    for (int mt = 0; mt < 4; mt++)
#pragma unroll
        for (int nt = 0; nt < 4; nt++)
#pragma unroll
            for (int q = 0; q < 4; q++) { accM[mt][nt][q] = 0.f; accC[mt][nt][q] = 0.f; }

    load_chunk(sb, xb, wb, 0, tid, xplane, wplane);
    asm volatile("cp.async.commit_group;" ::: "memory");

    for (int c = 0; c < NC; c++) {
        if (c + 1 < NC) {
            load_chunk(sb + ((c + 1) & 1) * BUFB, xb, wb, (c + 1) * 32, tid, xplane, wplane);
            asm volatile("cp.async.commit_group;" ::: "memory");
            asm volatile("cp.async.wait_group 1;" ::: "memory");
        } else {
            asm volatile("cp.async.wait_group 0;" ::: "memory");
        }
        __syncthreads();

        const uint32_t buf  = sb + (c & 1) * BUFB;
        const uint32_t Ab   = buf;
        const uint32_t Bb   = buf + 2 * PBY;

        // zero chunk accumulator (fresh per BK=32 chunk)
#pragma unroll
        for (int mt = 0; mt < 4; mt++)
#pragma unroll
            for (int nt = 0; nt < 4; nt++)
#pragma unroll
                for (int q = 0; q < 4; q++) accH[mt][nt][q] = 0.f;

#pragma unroll
        for (int ks = 0; ks < 4; ks++) {
            // B fragments, both planes, 2 np-groups (4 n8-tiles)
            uint32_t bf[2][2][4];
#pragma unroll
            for (int p = 0; p < 2; p++)
#pragma unroll
                for (int np = 0; np < 2; np++) {
                    int r  = warp_n + np * 16 + rB;
                    int ch = (ks * 2 + hB) ^ (r & 7);
                    ldsm4(bf[p][np], Bb + p * PBY + r * 128 + ch * 16);
                }
#pragma unroll
            for (int mt = 0; mt < 4; mt++) {
                int r  = warp_m + mt * 16 + rA;
                int ch = (ks * 2 + hA) ^ (r & 7);
                uint32_t a0f[4], a1f[4];
                ldsm4(a0f, Ab + r * 128 + ch * 16);            // t0 plane
#pragma unroll
                for (int nt = 0; nt < 4; nt++) {
                    // main: t0 * w0  -> chunk accumulator
                    mma_tf32(accH[mt][nt], a0f,
                             bf[0][nt >> 1][(nt & 1) * 2], bf[0][nt >> 1][(nt & 1) * 2 + 1]);
                    // corr: t0 * w1
                    mma_tf32(accC[mt][nt], a0f,
                             bf[1][nt >> 1][(nt & 1) * 2], bf[1][nt >> 1][(nt & 1) * 2 + 1]);
                }
                ldsm4(a1f, Ab + PBY + r * 128 + ch * 16);      // t1 plane
#pragma unroll
                for (int nt = 0; nt < 4; nt++) {
                    // corr: t1 * w0
                    mma_tf32(accC[mt][nt], a1f,
                             bf[0][nt >> 1][(nt & 1) * 2], bf[0][nt >> 1][(nt & 1) * 2 + 1]);
                }
            }
        }

        // fold chunk into master (rn add at full magnitude, once per chunk)
#pragma unroll
        for (int mt = 0; mt < 4; mt++)
#pragma unroll
            for (int nt = 0; nt < 4; nt++)
#pragma unroll
                for (int q = 0; q < 4; q++)
                    accM[mt][nt][q] = __fadd_rn(accM[mt][nt][q], accH[mt][nt][q]);

        __syncthreads();
    }

    // Epilogue: cur = main + corr
    float* __restrict__ cb = g_cur + (size_t)b * NT * NO;
#pragma unroll
    for (int mt = 0; mt < 4; mt++) {
        int r0 = t0 + warp_m + mt * 16 + (lane >> 2);
#pragma unroll
        for (int nt = 0; nt < 4; nt++) {
            int cc = n0 + warp_n + nt * 8 + (lane & 3) * 2;
            float2 v0, v1;
            v0.x = __fadd_rn(accM[mt][nt][0], accC[mt][nt][0]);
            v0.y = __fadd_rn(accM[mt][nt][1], accC[mt][nt][1]);
            v1.x = __fadd_rn(accM[mt][nt][2], accC[mt][nt][2]);
            v1.y = __fadd_rn(accM[mt][nt][3], accC[mt][nt][3]);
            if (r0 < NT)
                *reinterpret_cast<float2*>(cb + (size_t)r0 * NO + cc) = v0;
            if (r0 + 8 < NT)
                *reinterpret_cast<float2*>(cb + (size_t)(r0 + 8) * NO + cc) = v1;
        }
    }
}

// ---------------------------------------------------------------------------
// Scan: per (b,o) neuron, serial over t (exact reference rounding order).
// ---------------------------------------------------------------------------
#define TT 40   // 1000 % 40 == 0

__global__ __launch_bounds__(128)
void snn_scan_kernel(float* __restrict__ out)
{
    __shared__ float s[128][TT + 1];

    const int b  = blockIdx.y;
    const int o0 = blockIdx.x * 128;
    const int o  = o0 + threadIdx.x;

    const float* __restrict__ cb = g_cur + (size_t)b * NT * NO;
    const float DT = (float)(0.001 / 50.0);

    float v = 0.0f;

    for (int tc = 0; tc < NT; tc += TT) {
#pragma unroll
        for (int tt = 0; tt < TT; tt++) {
            float cur = cb[(size_t)(tc + tt) * NO + o];
            float d  = __fsub_rn(cur, v);
            float dv = __fmul_rn(d, DT);
            v = __fadd_rn(v, dv);
            bool sp = (v >= 1.0f);
            s[threadIdx.x][tt] = sp ? 1.0f : 0.0f;
            v = sp ? 0.0f : v;
        }
        __syncthreads();

        for (int idx = threadIdx.x; idx < 128 * TT; idx += 128) {
            int oo = idx / TT;
            int tt = idx - oo * TT;
            out[((size_t)b * NO + (o0 + oo)) * NT + tc + tt] = s[oo][tt];
        }
        __syncthreads();
    }
}

// ---------------------------------------------------------------------------
extern "C" void kernel_launch(void* const* d_in, const int* in_sizes, int n_in,
                              void* d_out, int out_size)
{
    const float* x = (const float*)d_in[0];   // [32, 1024, 1000]
    const float* w = (const float*)d_in[1];   // [1024, 1024]
    float* out = (float*)d_out;               // [32, 1024, 1000]

    (void)in_sizes; (void)n_in; (void)out_size;

    cudaFuncSetAttribute(snn_gemm_tf32, cudaFuncAttributeMaxDynamicSharedMemorySize, SMEMSZ);

    dim3 wgrid(NI / 32, NO / 32);                 // 32 x 32
    wconv_kernel<<<wgrid, dim3(32, 8)>>>(w);

    dim3 xgrid((NT + 31) / 32, NI / 32, NB);      // 32 x 32 x 32
    xconv_kernel<<<xgrid, dim3(32, 8)>>>(x);

    dim3 ggrid(NO / 128, NTP / 128, NB);          // 8 x 8 x 32
    snn_gemm_tf32<<<ggrid, 256, SMEMSZ>>>();

    dim3 sgrid(NO / 128, NB);                     // 8 x 32
    snn_scan_kernel<<<sgrid, 128>>>(out);
}

// round 11
// speedup vs baseline: 2.9921x; 2.7994x over previous
#include <cuda_runtime.h>
#include <cuda_fp16.h>
#include <cstdint>

// ---------------------------------------------------------------------------
// Problem shape
#define NB   32      // batch
#define NT   1000    // time steps
#define NO   1024    // n_out
#define NI   1024    // n_in (K)
#define NTP  1024    // padded T

// Scratch (__device__ globals zero-initialized; pad rows stay zero)
__device__ float g_cur[(size_t)NB * NT * NO];             // currents [b][t][o]
__device__ __half g_xh[(size_t)2 * NB * NTP * NI];        // x fp16 planes [p][b][t][k]
__device__ __half g_wh[(size_t)2 * NO * NI];              // w fp16 planes [p][n][k]

__device__ __forceinline__ uint32_t smem_u32(const void* p) {
    uint32_t a;
    asm("{ .reg .u64 t; cvta.to.shared.u64 t, %1; cvt.u32.u64 %0, t; }" : "=r"(a) : "l"(p));
    return a;
}

// fp32 -> 2x fp16 split (11+11 mantissa bits, same structure as tf32x2)
__device__ __forceinline__ void split2_f16(float v, __half& h0, __half& h1) {
    h0 = __float2half_rn(v);
    float r = __fsub_rn(v, __half2float(h0));
    h1 = __float2half_rn(r);
}

// ---------------------------------------------------------------------------
// wconv: w[k][n] (f32) -> g_wh[p][n][k] (fp16 planes, transposed)
// ---------------------------------------------------------------------------
__global__ __launch_bounds__(256)
void wconv_kernel(const float* __restrict__ w)
{
    __shared__ float tile[32][33];
    const int k0 = blockIdx.x * 32;
    const int n0 = blockIdx.y * 32;
    const int tx = threadIdx.x, ty = threadIdx.y;   // (32, 8)
#pragma unroll
    for (int j = 0; j < 4; j++) {
        int k = k0 + ty + 8 * j;
        tile[ty + 8 * j][tx] = w[(size_t)k * NO + n0 + tx];
    }
    __syncthreads();
#pragma unroll
    for (int j = 0; j < 4; j++) {
        int r = ty + 8 * j;
        int n = n0 + r;
        __half h0, h1;
        split2_f16(tile[tx][r], h0, h1);
        size_t base = (size_t)n * NI + k0 + tx;
        g_wh[base]                   = h0;
        g_wh[(size_t)NO * NI + base] = h1;
    }
}

// ---------------------------------------------------------------------------
// xconv: x[b][k][t] (f32) -> g_xh[p][b][t][k] (fp16 planes, transposed per b)
// ---------------------------------------------------------------------------
__global__ __launch_bounds__(256)
void xconv_kernel(const float* __restrict__ x)
{
    __shared__ float tile[32][33];
    const int b  = blockIdx.z;
    const int k0 = blockIdx.y * 32;
    const int t0 = blockIdx.x * 32;
    const int tx = threadIdx.x, ty = threadIdx.y;   // (32, 8)
    const float* xb = x + (size_t)b * NI * NT;
#pragma unroll
    for (int j = 0; j < 4; j++) {
        int k = k0 + ty + 8 * j;
        int t = t0 + tx;
        tile[ty + 8 * j][tx] = (t < NT) ? xb[(size_t)k * NT + t] : 0.0f;
    }
    __syncthreads();
    const size_t plane = (size_t)NB * NTP * NI;
#pragma unroll
    for (int j = 0; j < 4; j++) {
        int r = ty + 8 * j;
        int t = t0 + r;
        if (t < NT) {
            __half h0, h1;
            split2_f16(tile[tx][r], h0, h1);
            size_t base = ((size_t)b * NTP + t) * NI + k0 + tx;
            g_xh[base]         = h0;
            g_xh[plane + base] = h1;
        }
    }
}

// ---------------------------------------------------------------------------
// GEMM via mma.sync.m16n8k16.f16 (sm_80 path; 2x flops/instr vs tf32 k8).
// cur = sum_k x*w, fp32-emulated fp16x3:
//   main = h0x*h0w (two-level: zero-start chunk acc per BK=32, folded into
//   master with rn add — mirrors the verified R10 structure);
//   corr = h0x*h1w + h1x*h0w (chained second accumulator).
// Final cur = main + corr (one rn add).
// Block 256 thr (8 warps, 2m x 4n), CTA tile 128(t) x 128(o), BK=64 chunks,
// double-buffered cp.async, fold every 2 k16-steps (BK=32 granularity).
// ---------------------------------------------------------------------------
#define PB     16384             // one plane: 128 rows x 64 fp16 (128B rows)
#define BBASE  (2 * PB)          // B planes start within buffer
#define BUFB   (4 * PB)          // [A0][A1][B0][B1] = 64 KB
#define SMEMSZ (2 * BUFB)        // 128 KB
#define NC     16                // 1024 / 64 chunks

__device__ __forceinline__ void ldsm4(uint32_t* r, uint32_t addr) {
    asm volatile("ldmatrix.sync.aligned.m8n8.x4.shared.b16 {%0,%1,%2,%3}, [%4];"
        : "=r"(r[0]), "=r"(r[1]), "=r"(r[2]), "=r"(r[3]) : "r"(addr));
}
__device__ __forceinline__ void mma16816(float* d, const uint32_t* a, uint32_t b0, uint32_t b1) {
    asm volatile("mma.sync.aligned.m16n8k16.row.col.f32.f16.f16.f32 "
        "{%0,%1,%2,%3}, {%4,%5,%6,%7}, {%8,%9}, {%0,%1,%2,%3};"
        : "+f"(d[0]), "+f"(d[1]), "+f"(d[2]), "+f"(d[3])
        : "r"(a[0]), "r"(a[1]), "r"(a[2]), "r"(a[3]), "r"(b0), "r"(b1));
}

__device__ __forceinline__ void load_chunk(uint32_t sbuf,
                                           const __half* xb, const __half* wb,
                                           int k0, int tid,
                                           size_t xplane, size_t wplane)
{
    // 4096 16B units: [A0][A1][B0][B1], each 128 rows x 8 chunks of 16B
#pragma unroll
    for (int i = 0; i < 16; i++) {
        int v   = tid + i * 256;          // 0..4095
        int sec = v >> 10;                // 0..3
        int row = (v >> 3) & 127;
        int ch  = v & 7;
        const __half* g;
        if (sec < 2) g = xb + (size_t)(sec)     * xplane + (size_t)row * NI + k0 + ch * 8;
        else         g = wb + (size_t)(sec - 2) * wplane + (size_t)row * NI + k0 + ch * 8;
        uint32_t d = sbuf + sec * PB + row * 128 + ((ch ^ (row & 7)) * 16);
        asm volatile("cp.async.cg.shared.global [%0], [%1], 16;" :: "r"(d), "l"((const void*)g));
    }
}

__global__ __launch_bounds__(256, 1)
void snn_gemm_f16()
{
    extern __shared__ char smem[];
    const int tid  = threadIdx.x;
    const int lane = tid & 31;
    const int wid  = tid >> 5;

    const int b  = blockIdx.z;
    const int t0 = blockIdx.y * 128;
    const int n0 = blockIdx.x * 128;

    const size_t xplane = (size_t)NB * NTP * NI;
    const size_t wplane = (size_t)NO * NI;
    const __half* xb = g_xh + ((size_t)b * NTP + t0) * NI;
    const __half* wb = g_wh + (size_t)n0 * NI;

    const uint32_t sb = smem_u32(smem);

    const int warp_m = (wid >> 2) * 64;    // 0 / 64
    const int warp_n = (wid & 3) * 32;     // 0..96

    // ldmatrix per-lane components (validated layout from R9)
    const int rA = (lane & 7) + ((lane >> 3) & 1) * 8;
    const int cA = (lane >> 4) & 1;
    const int rB = (lane & 7) + ((lane >> 4) & 1) * 8;
    const int cB = (lane >> 3) & 1;

    float accM[4][4][4], accC[4][4][4], accH[4][4][4];
#pragma unroll
    for (int mt = 0; mt < 4; mt++)
#pragma unroll
        for (int nt = 0; nt < 4; nt++)
#pragma unroll
            for (int q = 0; q < 4; q++) { accM[mt][nt][q] = 0.f; accC[mt][nt][q] = 0.f; }

    load_chunk(sb, xb, wb, 0, tid, xplane, wplane);
    asm volatile("cp.async.commit_group;" ::: "memory");

    for (int c = 0; c < NC; c++) {
        if (c + 1 < NC) {
            load_chunk(sb + ((c + 1) & 1) * BUFB, xb, wb, (c + 1) * 64, tid, xplane, wplane);
            asm volatile("cp.async.commit_group;" ::: "memory");
            asm volatile("cp.async.wait_group 1;" ::: "memory");
        } else {
            asm volatile("cp.async.wait_group 0;" ::: "memory");
        }
        __syncthreads();

        const uint32_t Ab = sb + (c & 1) * BUFB;
        const uint32_t Bb = Ab + BBASE;

        // Two BK=32 halves per chunk; fresh chunk accumulator each half
#pragma unroll
        for (int half = 0; half < 2; half++) {
#pragma unroll
            for (int mt = 0; mt < 4; mt++)
#pragma unroll
                for (int nt = 0; nt < 4; nt++)
#pragma unroll
                    for (int q = 0; q < 4; q++) accH[mt][nt][q] = 0.f;

#pragma unroll
            for (int kss = 0; kss < 2; kss++) {
                const int ks = half * 2 + kss;
                // B fragments: 2 planes x 2 n16-groups
                uint32_t bf[2][2][4];
#pragma unroll
                for (int p = 0; p < 2; p++)
#pragma unroll
                    for (int np = 0; np < 2; np++) {
                        int r  = warp_n + np * 16 + rB;
                        int ch = (ks * 2 + cB) ^ (r & 7);
                        ldsm4(bf[p][np], Bb + p * PB + r * 128 + ch * 16);
                    }
#pragma unroll
                for (int mt = 0; mt < 4; mt++) {
                    int r  = warp_m + mt * 16 + rA;
                    int ch = (ks * 2 + cA) ^ (r & 7);
                    uint32_t a0f[4], a1f[4];
                    ldsm4(a0f, Ab + r * 128 + ch * 16);          // h0 plane
#pragma unroll
                    for (int nt = 0; nt < 4; nt++) {
                        // main: h0x * h0w -> chunk accumulator
                        mma16816(accH[mt][nt], a0f,
                                 bf[0][nt >> 1][(nt & 1) * 2], bf[0][nt >> 1][(nt & 1) * 2 + 1]);
                        // corr: h0x * h1w
                        mma16816(accC[mt][nt], a0f,
                                 bf[1][nt >> 1][(nt & 1) * 2], bf[1][nt >> 1][(nt & 1) * 2 + 1]);
                    }
                    ldsm4(a1f, Ab + PB + r * 128 + ch * 16);     // h1 plane
#pragma unroll
                    for (int nt = 0; nt < 4; nt++) {
                        // corr: h1x * h0w
                        mma16816(accC[mt][nt], a1f,
                                 bf[0][nt >> 1][(nt & 1) * 2], bf[0][nt >> 1][(nt & 1) * 2 + 1]);
                    }
                }
            }

            // fold BK=32 chunk into master (rn add at full magnitude)
#pragma unroll
            for (int mt = 0; mt < 4; mt++)
#pragma unroll
                for (int nt = 0; nt < 4; nt++)
#pragma unroll
                    for (int q = 0; q < 4; q++)
                        accM[mt][nt][q] = __fadd_rn(accM[mt][nt][q], accH[mt][nt][q]);
        }
        __syncthreads();
    }

    // Epilogue: cur = main + corr
    float* __restrict__ cb = g_cur + (size_t)b * NT * NO;
#pragma unroll
    for (int mt = 0; mt < 4; mt++) {
        int r0 = t0 + warp_m + mt * 16 + (lane >> 2);
#pragma unroll
        for (int nt = 0; nt < 4; nt++) {
            int cc = n0 + warp_n + nt * 8 + (lane & 3) * 2;
            float2 v0, v1;
            v0.x = __fadd_rn(accM[mt][nt][0], accC[mt][nt][0]);
            v0.y = __fadd_rn(accM[mt][nt][1], accC[mt][nt][1]);
            v1.x = __fadd_rn(accM[mt][nt][2], accC[mt][nt][2]);
            v1.y = __fadd_rn(accM[mt][nt][3], accC[mt][nt][3]);
            if (r0 < NT)
                *reinterpret_cast<float2*>(cb + (size_t)r0 * NO + cc) = v0;
            if (r0 + 8 < NT)
                *reinterpret_cast<float2*>(cb + (size_t)(r0 + 8) * NO + cc) = v1;
        }
    }
}

// ---------------------------------------------------------------------------
// Scan: per (b,o) neuron, serial over t (exact reference rounding order).
// ---------------------------------------------------------------------------
#define TT 40   // 1000 % 40 == 0

__global__ __launch_bounds__(128)
void snn_scan_kernel(float* __restrict__ out)
{
    __shared__ float s[128][TT + 1];

    const int b  = blockIdx.y;
    const int o0 = blockIdx.x * 128;
    const int o  = o0 + threadIdx.x;

    const float* __restrict__ cb = g_cur + (size_t)b * NT * NO;
    const float DT = (float)(0.001 / 50.0);

    float v = 0.0f;

    for (int tc = 0; tc < NT; tc += TT) {
#pragma unroll
        for (int tt = 0; tt < TT; tt++) {
            float cur = cb[(size_t)(tc + tt) * NO + o];
            float d  = __fsub_rn(cur, v);
            float dv = __fmul_rn(d, DT);
            v = __fadd_rn(v, dv);
            bool sp = (v >= 1.0f);
            s[threadIdx.x][tt] = sp ? 1.0f : 0.0f;
            v = sp ? 0.0f : v;
        }
        __syncthreads();

        for (int idx = threadIdx.x; idx < 128 * TT; idx += 128) {
            int oo = idx / TT;
            int tt = idx - oo * TT;
            out[((size_t)b * NO + (o0 + oo)) * NT + tc + tt] = s[oo][tt];
        }
        __syncthreads();
    }
}

// ---------------------------------------------------------------------------
extern "C" void kernel_launch(void* const* d_in, const int* in_sizes, int n_in,
                              void* d_out, int out_size)
{
    const float* x = (const float*)d_in[0];   // [32, 1024, 1000]
    const float* w = (const float*)d_in[1];   // [1024, 1024]
    float* out = (float*)d_out;               // [32, 1024, 1000]

    (void)in_sizes; (void)n_in; (void)out_size;

    cudaFuncSetAttribute(snn_gemm_f16, cudaFuncAttributeMaxDynamicSharedMemorySize, SMEMSZ);

    dim3 wgrid(NI / 32, NO / 32);                 // 32 x 32
    wconv_kernel<<<wgrid, dim3(32, 8)>>>(w);

    dim3 xgrid((NT + 31) / 32, NI / 32, NB);      // 32 x 32 x 32
    xconv_kernel<<<xgrid, dim3(32, 8)>>>(x);

    dim3 ggrid(NO / 128, NTP / 128, NB);          // 8 x 8 x 32
    snn_gemm_f16<<<ggrid, 256, SMEMSZ>>>();

    dim3 sgrid(NO / 128, NB);                     // 8 x 32
    snn_scan_kernel<<<sgrid, 128>>>(out);
}